// round 1
// baseline (speedup 1.0000x reference)
#include <cuda_runtime.h>
#include <math.h>

#define BB 8
#define SS 1024
#define DD 1024
#define NH 16
#define HH 64
#define MROWS (BB*SS)            // 8192
#define Y_SIZE (BB*SS*DD)        // 8388608

// Scratch (no allocations allowed)
__device__ float g_logits[NH*BB*SS*HH];   // [n][b][s][h]
__device__ float g_outh[BB*SS*NH*HH];     // [b][s][n*H+h]  (concat layout)
__device__ float g_ypre[BB*SS*DD];        // pre-layernorm y

// ---------------------------------------------------------------------------
// Kernel A: logits[n, r, h] = sum_d x[r, d] * w[n, d, h]
// 128x64 tile per block, 256 threads, thread tile 8x4, K chunk 16
// ---------------------------------------------------------------------------
__global__ __launch_bounds__(256) void proj_kernel(const float* __restrict__ x,
                                                   const float* __restrict__ w) {
    __shared__ float xs[16][132];   // transposed [k][r], padded
    __shared__ float ws[16][64];    // [k][h]
    const int n  = blockIdx.y;
    const int r0 = blockIdx.x * 128;
    const int tid = threadIdx.x;
    const float* wn = w + n * (DD * HH);

    const int ry = tid >> 4;        // 0..15 -> rows ry*8..+7
    const int cx = tid & 15;        // 0..15 -> cols cx*4..+3

    float acc[8][4] = {};

    for (int k0 = 0; k0 < DD; k0 += 16) {
        #pragma unroll
        for (int it = 0; it < 8; it++) {
            int idx = tid + it * 256;          // 2048 elems
            int kk = idx & 15, rr = idx >> 4;
            xs[kk][rr] = x[(r0 + rr) * DD + k0 + kk];
        }
        #pragma unroll
        for (int it = 0; it < 4; it++) {
            int idx = tid + it * 256;          // 1024 elems
            int kk = idx >> 6, hh2 = idx & 63;
            ws[kk][hh2] = wn[(k0 + kk) * HH + hh2];
        }
        __syncthreads();
        #pragma unroll
        for (int kk = 0; kk < 16; kk++) {
            float4 a0 = *(const float4*)&xs[kk][ry * 8];
            float4 a1 = *(const float4*)&xs[kk][ry * 8 + 4];
            float4 bv = *(const float4*)&ws[kk][cx * 4];
            float av[8] = {a0.x, a0.y, a0.z, a0.w, a1.x, a1.y, a1.z, a1.w};
            float bvv[4] = {bv.x, bv.y, bv.z, bv.w};
            #pragma unroll
            for (int i = 0; i < 8; i++)
                #pragma unroll
                for (int j = 0; j < 4; j++)
                    acc[i][j] += av[i] * bvv[j];
        }
        __syncthreads();
    }

    float* lp = g_logits + n * (BB * SS * HH);
    #pragma unroll
    for (int i = 0; i < 8; i++) {
        int r = r0 + ry * 8 + i;
        float4 v = make_float4(acc[i][0], acc[i][1], acc[i][2], acc[i][3]);
        *(float4*)&lp[r * HH + cx * 4] = v;
    }
}

// ---------------------------------------------------------------------------
// Kernel B: fused attention per (n, b, 32-row tile)
//   scores[32][1024] in smem -> softmax -> write attn -> out = P @ V
// Dynamic smem layout (floats):
//   scores: 32 * 1028            = 32896
//   qT    : 64 * 36              =  2304
//   kts   : 64 * 132 (>= 64*64)  =  8448     total 43648 floats = 174592 B
// ---------------------------------------------------------------------------
#define SMEMB_FLOATS (32*1028 + 64*36 + 64*132)

__global__ __launch_bounds__(256) void attn_kernel(float* __restrict__ out_attn) {
    extern __shared__ float smemB[];
    float* scores = smemB;
    float* qT     = smemB + 32 * 1028;
    float* kts    = smemB + 32 * 1028 + 64 * 36;
    __shared__ float rs[32];

    const int rt = blockIdx.x;   // 0..31 row tile
    const int b  = blockIdx.y;   // 0..7
    const int n  = blockIdx.z;   // 0..15
    const int s0 = rt * 32;
    const int tid = threadIdx.x;
    const float* lp = g_logits + n * (BB * SS * HH) + b * (SS * HH);

    // load Q tile transposed: qT[h][i]
    #pragma unroll
    for (int it = 0; it < 8; it++) {
        int idx = tid + it * 256;       // 2048
        int i = idx >> 6, h = idx & 63;
        qT[h * 36 + i] = lp[(s0 + i) * HH + h];
    }

    // ---- scores = scale * Q K^T, tiles of 128 keys ----
    const int ry = tid >> 5;   // 0..7 -> rows ry*4..+3
    const int cx = tid & 31;   // 0..31 -> cols cx*4..+3
    const float scale = 0.125f;
    for (int kt = 0; kt < 8; kt++) {
        __syncthreads();
        #pragma unroll
        for (int it = 0; it < 32; it++) {
            int idx = tid + it * 256;   // 8192
            int j = idx >> 6, h = idx & 63;
            kts[h * 132 + j] = lp[(kt * 128 + j) * HH + h];
        }
        __syncthreads();
        float acc[4][4] = {};
        #pragma unroll
        for (int h = 0; h < 64; h++) {
            float4 a  = *(const float4*)&qT[h * 36 + ry * 4];
            float4 bv = *(const float4*)&kts[h * 132 + cx * 4];
            float av[4] = {a.x, a.y, a.z, a.w};
            float bvv[4] = {bv.x, bv.y, bv.z, bv.w};
            #pragma unroll
            for (int i = 0; i < 4; i++)
                #pragma unroll
                for (int j = 0; j < 4; j++)
                    acc[i][j] += av[i] * bvv[j];
        }
        #pragma unroll
        for (int i = 0; i < 4; i++) {
            float4 v = make_float4(acc[i][0] * scale, acc[i][1] * scale,
                                   acc[i][2] * scale, acc[i][3] * scale);
            *(float4*)&scores[(ry * 4 + i) * 1028 + kt * 128 + cx * 4] = v;
        }
    }
    __syncthreads();

    // ---- softmax: row = tid/8, 8 threads per row scan 128 each ----
    {
        const int row = tid >> 3, c = tid & 7;
        float* srow = scores + row * 1028 + c * 128;
        float m = -1e30f;
        #pragma unroll 8
        for (int i = 0; i < 128; i++) m = fmaxf(m, srow[i]);
        m = fmaxf(m, __shfl_xor_sync(0xffffffffu, m, 1));
        m = fmaxf(m, __shfl_xor_sync(0xffffffffu, m, 2));
        m = fmaxf(m, __shfl_xor_sync(0xffffffffu, m, 4));
        float sum = 0.f;
        #pragma unroll 8
        for (int i = 0; i < 128; i++) {
            float e = __expf(srow[i] - m);
            srow[i] = e;
            sum += e;
        }
        sum += __shfl_xor_sync(0xffffffffu, sum, 1);
        sum += __shfl_xor_sync(0xffffffffu, sum, 2);
        sum += __shfl_xor_sync(0xffffffffu, sum, 4);
        if (c == 0) rs[row] = 1.0f / sum;
    }
    __syncthreads();

    // ---- write normalized attention to d_out ----
    {
        float* ap = out_attn + ((size_t)(n * BB + b)) * SS * SS + (size_t)s0 * SS;
        #pragma unroll
        for (int it = 0; it < 32; it++) {
            int idx = tid + it * 256;            // 8192 float4s
            int r = idx >> 8;
            int c4 = (idx & 255) << 2;
            float4 v = *(const float4*)&scores[r * 1028 + c4];
            float iv = rs[r];
            v.x *= iv; v.y *= iv; v.z *= iv; v.w *= iv;
            *(float4*)&ap[(size_t)r * SS + c4] = v;
        }
    }

    // ---- out = P @ V (unnormalized P in smem, scale by rs at the end) ----
    const int py  = tid >> 4;   // 0..15 -> rows py*2..+1
    const int pxc = tid & 15;   // 0..15 -> cols pxc*4..+3
    float pacc[2][4] = {};
    float* vt = kts;            // reuse as [64][64] (no pad)
    for (int jt = 0; jt < 16; jt++) {
        __syncthreads();
        #pragma unroll
        for (int it = 0; it < 16; it++) {
            int idx = tid + it * 256;   // 4096
            int j = idx >> 6, h = idx & 63;
            vt[j * 64 + h] = lp[(jt * 64 + j) * HH + h];
        }
        __syncthreads();
        #pragma unroll 16
        for (int j = 0; j < 64; j++) {
            float p0 = scores[(py * 2) * 1028 + jt * 64 + j];
            float p1 = scores[(py * 2 + 1) * 1028 + jt * 64 + j];
            float4 vv = *(const float4*)&vt[j * 64 + pxc * 4];
            pacc[0][0] += p0 * vv.x; pacc[0][1] += p0 * vv.y;
            pacc[0][2] += p0 * vv.z; pacc[0][3] += p0 * vv.w;
            pacc[1][0] += p1 * vv.x; pacc[1][1] += p1 * vv.y;
            pacc[1][2] += p1 * vv.z; pacc[1][3] += p1 * vv.w;
        }
    }
    {
        float i0 = rs[py * 2], i1 = rs[py * 2 + 1];
        int r0g = b * SS + s0 + py * 2;
        float4 v0 = make_float4(pacc[0][0]*i0, pacc[0][1]*i0, pacc[0][2]*i0, pacc[0][3]*i0);
        float4 v1 = make_float4(pacc[1][0]*i1, pacc[1][1]*i1, pacc[1][2]*i1, pacc[1][3]*i1);
        *(float4*)&g_outh[r0g * 1024 + n * 64 + pxc * 4] = v0;
        *(float4*)&g_outh[(r0g + 1) * 1024 + n * 64 + pxc * 4] = v1;
    }
}

// ---------------------------------------------------------------------------
// Kernel C: ypre[r, d] = x[r, d] + lin_b[d] + sum_k outh[r, k] * lin_w[d, k]
// 128x128 tile, 256 threads, thread tile 8x8, K chunk 16
// ---------------------------------------------------------------------------
__global__ __launch_bounds__(256) void outproj_kernel(const float* __restrict__ x,
                                                      const float* __restrict__ lw,
                                                      const float* __restrict__ lb) {
    __shared__ float aT[16][132];
    __shared__ float wS[16][132];
    const int r0 = blockIdx.x * 128;
    const int d0 = blockIdx.y * 128;
    const int tid = threadIdx.x;
    const int ry = tid >> 4;   // rows ry*8..+7
    const int cx = tid & 15;   // cols cx*8..+7

    float acc[8][8] = {};

    for (int k0 = 0; k0 < 1024; k0 += 16) {
        #pragma unroll
        for (int it = 0; it < 8; it++) {
            int idx = tid + it * 256;
            int kk = idx & 15, rr = idx >> 4;
            aT[kk][rr] = g_outh[(r0 + rr) * 1024 + k0 + kk];
            wS[kk][rr] = lw[(d0 + rr) * 1024 + k0 + kk];
        }
        __syncthreads();
        #pragma unroll
        for (int kk = 0; kk < 16; kk++) {
            float4 a0 = *(const float4*)&aT[kk][ry * 8];
            float4 a1 = *(const float4*)&aT[kk][ry * 8 + 4];
            float4 b0 = *(const float4*)&wS[kk][cx * 8];
            float4 b1 = *(const float4*)&wS[kk][cx * 8 + 4];
            float av[8] = {a0.x, a0.y, a0.z, a0.w, a1.x, a1.y, a1.z, a1.w};
            float bv[8] = {b0.x, b0.y, b0.z, b0.w, b1.x, b1.y, b1.z, b1.w};
            #pragma unroll
            for (int i = 0; i < 8; i++)
                #pragma unroll
                for (int j = 0; j < 8; j++)
                    acc[i][j] += av[i] * bv[j];
        }
        __syncthreads();
    }

    #pragma unroll
    for (int i = 0; i < 8; i++) {
        int r = r0 + ry * 8 + i;
        #pragma unroll
        for (int jj = 0; jj < 2; jj++) {
            int d = d0 + cx * 8 + jj * 4;
            float4 xv = *(const float4*)&x[r * 1024 + d];
            float4 bv = *(const float4*)&lb[d];
            float4 o;
            o.x = acc[i][jj * 4 + 0] + xv.x + bv.x;
            o.y = acc[i][jj * 4 + 1] + xv.y + bv.y;
            o.z = acc[i][jj * 4 + 2] + xv.z + bv.z;
            o.w = acc[i][jj * 4 + 3] + xv.w + bv.w;
            *(float4*)&g_ypre[r * 1024 + d] = o;
        }
    }
}

// ---------------------------------------------------------------------------
// Kernel D: layernorm per row of 1024, one block per row
// ---------------------------------------------------------------------------
__global__ __launch_bounds__(256) void ln_kernel(float* __restrict__ y,
                                                 const float* __restrict__ g,
                                                 const float* __restrict__ bfn) {
    const int r = blockIdx.x;
    const int tid = threadIdx.x;
    const int lane = tid & 31, wid = tid >> 5;
    __shared__ float red1[8];
    __shared__ float red2[8];
    __shared__ float sh_mu, sh_rstd;

    float4 v = *(const float4*)&g_ypre[r * 1024 + tid * 4];
    float s = v.x + v.y + v.z + v.w;
    #pragma unroll
    for (int o = 16; o > 0; o >>= 1) s += __shfl_xor_sync(0xffffffffu, s, o);
    if (lane == 0) red1[wid] = s;
    __syncthreads();
    if (tid == 0) {
        float t = 0.f;
        #pragma unroll
        for (int i = 0; i < 8; i++) t += red1[i];
        sh_mu = t * (1.0f / 1024.0f);
    }
    __syncthreads();
    float mu = sh_mu;
    float dx = v.x - mu, dy = v.y - mu, dz = v.z - mu, dw = v.w - mu;
    float sq = dx * dx + dy * dy + dz * dz + dw * dw;
    #pragma unroll
    for (int o = 16; o > 0; o >>= 1) sq += __shfl_xor_sync(0xffffffffu, sq, o);
    if (lane == 0) red2[wid] = sq;
    __syncthreads();
    if (tid == 0) {
        float t = 0.f;
        #pragma unroll
        for (int i = 0; i < 8; i++) t += red2[i];
        sh_rstd = rsqrtf(t * (1.0f / 1024.0f) + 1e-5f);
    }
    __syncthreads();
    float rstd = sh_rstd;
    float4 gv = *(const float4*)&g[tid * 4];
    float4 bv = *(const float4*)&bfn[tid * 4];
    float4 o;
    o.x = dx * rstd * gv.x + bv.x;
    o.y = dy * rstd * gv.y + bv.y;
    o.z = dz * rstd * gv.z + bv.z;
    o.w = dw * rstd * gv.w + bv.w;
    *(float4*)&y[r * 1024 + tid * 4] = o;
}

// ---------------------------------------------------------------------------
extern "C" void kernel_launch(void* const* d_in, const int* in_sizes, int n_in,
                              void* d_out, int out_size) {
    const float* x   = (const float*)d_in[0];
    const float* w   = (const float*)d_in[1];
    const float* lw  = (const float*)d_in[2];
    const float* lb  = (const float*)d_in[3];
    const float* lng = (const float*)d_in[4];
    const float* lnb = (const float*)d_in[5];
    float* out = (float*)d_out;

    const int smemB = SMEMB_FLOATS * (int)sizeof(float);   // 174592 B
    cudaFuncSetAttribute(attn_kernel, cudaFuncAttributeMaxDynamicSharedMemorySize, smemB);

    proj_kernel<<<dim3(64, 16), 256>>>(x, w);
    attn_kernel<<<dim3(32, 8, 16), 256, smemB>>>(out + Y_SIZE);
    outproj_kernel<<<dim3(64, 8), 256>>>(x, lw, lb);
    ln_kernel<<<MROWS, 256>>>(out, lng, lnb);
}

// round 5
// speedup vs baseline: 1.9047x; 1.9047x over previous
#include <cuda_runtime.h>
#include <cuda_bf16.h>
#include <cstdint>
#include <math.h>

#define BB 8
#define SS 1024
#define DD 1024
#define NH 16
#define HH 64
#define MROWS (BB*SS)            // 8192
#define Y_SIZE (BB*SS*DD)        // 8388608

// ---------------------------------------------------------------------------
// Scratch (device globals; no allocations allowed)
// ---------------------------------------------------------------------------
__device__ float g_ypre[MROWS*DD];                         // pre-layernorm y
__device__ __nv_bfloat16 g_xhi[MROWS*DD], g_xlo[MROWS*DD]; // x split
__device__ __nv_bfloat16 g_wThi[DD*DD], g_wTlo[DD*DD];     // proj B: [c=n*64+h][d]
__device__ __nv_bfloat16 g_lwhi[DD*DD], g_lwlo[DD*DD];     // outproj B: [d][k]
__device__ __nv_bfloat16 g_lhi[MROWS*DD], g_llo[MROWS*DD]; // logits split [r][n*64+h]
__device__ __nv_bfloat16 g_ohhi[MROWS*DD], g_ohlo[MROWS*DD]; // attn heads out split

// ---------------------------------------------------------------------------
// mma.sync / ldmatrix helpers (base ISA — works on sm_103 target)
// ---------------------------------------------------------------------------
__device__ __forceinline__ uint32_t smem_u32(const void* p) {
    uint32_t a;
    asm("{ .reg .u64 t; cvta.to.shared.u64 t, %1; cvt.u32.u64 %0, t; }" : "=r"(a) : "l"(p));
    return a;
}

__device__ __forceinline__ void mma_bf16(float c[4],
                                         unsigned a0, unsigned a1, unsigned a2, unsigned a3,
                                         unsigned b0, unsigned b1) {
    asm volatile("mma.sync.aligned.m16n8k16.row.col.f32.bf16.bf16.f32 "
        "{%0,%1,%2,%3}, {%4,%5,%6,%7}, {%8,%9}, {%0,%1,%2,%3};"
        : "+f"(c[0]), "+f"(c[1]), "+f"(c[2]), "+f"(c[3])
        : "r"(a0), "r"(a1), "r"(a2), "r"(a3), "r"(b0), "r"(b1));
}

__device__ __forceinline__ void ldsm4(unsigned r[4], uint32_t addr) {
    asm volatile("ldmatrix.sync.aligned.m8n8.x4.shared.b16 {%0,%1,%2,%3}, [%4];"
        : "=r"(r[0]), "=r"(r[1]), "=r"(r[2]), "=r"(r[3]) : "r"(addr));
}
__device__ __forceinline__ void ldsm4t(unsigned r[4], uint32_t addr) {
    asm volatile("ldmatrix.sync.aligned.m8n8.x4.trans.shared.b16 {%0,%1,%2,%3}, [%4];"
        : "=r"(r[0]), "=r"(r[1]), "=r"(r[2]), "=r"(r[3]) : "r"(addr));
}

// ---------------------------------------------------------------------------
// Converters: fp32 -> bf16 hi/lo split
// ---------------------------------------------------------------------------
__global__ __launch_bounds__(256) void split4_kernel(const float* __restrict__ s,
                                                     __nv_bfloat16* __restrict__ hi,
                                                     __nv_bfloat16* __restrict__ lo, int n4) {
    int i = blockIdx.x * 256 + threadIdx.x;
    if (i >= n4) return;
    float4 v = ((const float4*)s)[i];
    __nv_bfloat16 h0 = __float2bfloat16(v.x), h1 = __float2bfloat16(v.y);
    __nv_bfloat16 h2 = __float2bfloat16(v.z), h3 = __float2bfloat16(v.w);
    __nv_bfloat162* hp = (__nv_bfloat162*)hi;
    __nv_bfloat162* lp = (__nv_bfloat162*)lo;
    hp[i*2]   = __nv_bfloat162(h0, h1);
    hp[i*2+1] = __nv_bfloat162(h2, h3);
    lp[i*2]   = __nv_bfloat162(__float2bfloat16(v.x - __bfloat162float(h0)),
                               __float2bfloat16(v.y - __bfloat162float(h1)));
    lp[i*2+1] = __nv_bfloat162(__float2bfloat16(v.z - __bfloat162float(h2)),
                               __float2bfloat16(v.w - __bfloat162float(h3)));
}

// w [NH][DD][HH] -> wT[c=n*64+h][d], split hi/lo
__global__ __launch_bounds__(256) void convw_kernel(const float* __restrict__ w) {
    int o = blockIdx.x * 256 + threadIdx.x;
    int c = o >> 10, d = o & 1023;
    int n = c >> 6, h = c & 63;
    float v = __ldg(&w[(n * 1024 + d) * 64 + h]);
    __nv_bfloat16 hv = __float2bfloat16(v);
    g_wThi[o] = hv;
    g_wTlo[o] = __float2bfloat16(v - __bfloat162float(hv));
}

// ---------------------------------------------------------------------------
// Dense GEMM via mma.sync: C[8192,1024] = A @ B^T  (bf16 hi/lo 3-pass)
// Block tile 128x128, K chunk 64. 8 warps (2m x 4n), warp tile 64x32.
// Smem rows stride 72 bf16 (144B) -> conflict-free ldmatrix.
// EPI 0: write C as bf16 hi/lo. EPI 1: write fp32 C = acc + RX + BIAS.
// ---------------------------------------------------------------------------
#define GA_H 0
#define GA_L 18432
#define GB_H 36864
#define GB_L 55296
#define GSMEM 73728

template<int EPI>
__global__ __launch_bounds__(256) void gemm_mma(
    const __nv_bfloat16* __restrict__ Ah, const __nv_bfloat16* __restrict__ Al,
    const __nv_bfloat16* __restrict__ Bh, const __nv_bfloat16* __restrict__ Bl,
    __nv_bfloat16* __restrict__ Chi, __nv_bfloat16* __restrict__ Clo,
    float* __restrict__ Cf, const float* __restrict__ RX, const float* __restrict__ BIAS)
{
    extern __shared__ char sm[];
    const uint32_t sb = smem_u32(sm);
    const int tid = threadIdx.x, w = tid >> 5, lane = tid & 31;
    const int wm = w >> 2, wn = w & 3;
    const int r0 = blockIdx.x * 128, c0 = blockIdx.y * 128;

    float acc[4][4][4] = {};        // [mi][n8 group][4]
    const int lrow = tid >> 3, lc8 = tid & 7;

    #pragma unroll 1
    for (int k0 = 0; k0 < 1024; k0 += 64) {
        __syncthreads();
        #pragma unroll
        for (int it = 0; it < 4; it++) {
            int rr = lrow + it * 32;
            size_t goA = (size_t)(r0 + rr) * 1024 + k0 + lc8 * 8;
            size_t goB = (size_t)(c0 + rr) * 1024 + k0 + lc8 * 8;
            uint32_t so = (rr * 72 + lc8 * 8) * 2;
            *(uint4*)(sm + GA_H + so) = *(const uint4*)(Ah + goA);
            *(uint4*)(sm + GA_L + so) = *(const uint4*)(Al + goA);
            *(uint4*)(sm + GB_H + so) = *(const uint4*)(Bh + goB);
            *(uint4*)(sm + GB_L + so) = *(const uint4*)(Bl + goB);
        }
        __syncthreads();
        #pragma unroll
        for (int ks = 0; ks < 4; ks++) {
            unsigned ah[4][4], al[4][4], bh[2][4], bl[2][4];
            uint32_t abase = sb + ((wm * 64 + (lane & 15)) * 72 + ks * 16 + (lane >> 4) * 8) * 2;
            #pragma unroll
            for (int mi = 0; mi < 4; mi++) {
                ldsm4(ah[mi], abase + GA_H + mi * 2304);
                ldsm4(al[mi], abase + GA_L + mi * 2304);
            }
            uint32_t bbase = sb + ((wn * 32 + (lane & 15)) * 72 + ks * 16 + (lane >> 4) * 8) * 2;
            #pragma unroll
            for (int ni = 0; ni < 2; ni++) {
                ldsm4(bh[ni], bbase + GB_H + ni * 2304);
                ldsm4(bl[ni], bbase + GB_L + ni * 2304);
            }
            #pragma unroll
            for (int mi = 0; mi < 4; mi++)
                #pragma unroll
                for (int ni = 0; ni < 2; ni++) {
                    // non-trans B pairing: group0 {r0,r2}, group1 {r1,r3}
                    mma_bf16(acc[mi][2*ni],   ah[mi][0],ah[mi][1],ah[mi][2],ah[mi][3], bh[ni][0], bh[ni][2]);
                    mma_bf16(acc[mi][2*ni+1], ah[mi][0],ah[mi][1],ah[mi][2],ah[mi][3], bh[ni][1], bh[ni][3]);
                    mma_bf16(acc[mi][2*ni],   ah[mi][0],ah[mi][1],ah[mi][2],ah[mi][3], bl[ni][0], bl[ni][2]);
                    mma_bf16(acc[mi][2*ni+1], ah[mi][0],ah[mi][1],ah[mi][2],ah[mi][3], bl[ni][1], bl[ni][3]);
                    mma_bf16(acc[mi][2*ni],   al[mi][0],al[mi][1],al[mi][2],al[mi][3], bh[ni][0], bh[ni][2]);
                    mma_bf16(acc[mi][2*ni+1], al[mi][0],al[mi][1],al[mi][2],al[mi][3], bh[ni][1], bh[ni][3]);
                }
        }
    }

    // epilogue
    #pragma unroll
    for (int mi = 0; mi < 4; mi++) {
        int rr = r0 + wm * 64 + mi * 16 + (lane >> 2);
        #pragma unroll
        for (int nj = 0; nj < 4; nj++) {
            int cc = c0 + wn * 32 + nj * 8 + 2 * (lane & 3);
            if (EPI == 0) {
                #pragma unroll
                for (int half = 0; half < 2; half++) {
                    float v0 = acc[mi][nj][half*2], v1 = acc[mi][nj][half*2+1];
                    __nv_bfloat16 h0 = __float2bfloat16(v0), h1 = __float2bfloat16(v1);
                    size_t go = (size_t)(rr + half*8) * 1024 + cc;
                    *(__nv_bfloat162*)(Chi + go) = __nv_bfloat162(h0, h1);
                    *(__nv_bfloat162*)(Clo + go) = __nv_bfloat162(
                        __float2bfloat16(v0 - __bfloat162float(h0)),
                        __float2bfloat16(v1 - __bfloat162float(h1)));
                }
            } else {
                #pragma unroll
                for (int half = 0; half < 2; half++) {
                    size_t go = (size_t)(rr + half*8) * 1024 + cc;
                    float2 xv = *(const float2*)(RX + go);
                    float2 bv = *(const float2*)(BIAS + cc);
                    float2 o;
                    o.x = acc[mi][nj][half*2]   + xv.x + bv.x;
                    o.y = acc[mi][nj][half*2+1] + xv.y + bv.y;
                    *(float2*)(Cf + go) = o;
                }
            }
        }
    }
}

// ---------------------------------------------------------------------------
// Fused attention per (n, b, 32-row tile), tensorized.
//   QK^T (mma, 3-pass) -> fp32 scores smem -> fp32 softmax -> write attn
//   -> P split hi/lo per key tile -> P@V (mma, 3-pass) -> outh bf16 hi/lo
// ---------------------------------------------------------------------------
#define A_SC 0                      // scores: 32 x 1028 fp32 = 131584 B
#define A_QH 131584                 // 32 x 72 bf16 = 4608
#define A_QL 136192
#define A_KH 140800                 // 128 x 72 bf16 = 18432 (reused for V)
#define A_KL 159232
#define A_PH 177664                 // 32 x 136 bf16 = 8704
#define A_PL 186368
#define ASMEM 195072

__global__ __launch_bounds__(256) void attn_kernel(
    const __nv_bfloat16* __restrict__ LHI, const __nv_bfloat16* __restrict__ LLO,
    float* __restrict__ out_attn,
    __nv_bfloat16* __restrict__ OHI, __nv_bfloat16* __restrict__ OLO)
{
    extern __shared__ char sm[];
    const uint32_t sb = smem_u32(sm);
    float* scores = (float*)sm;
    __shared__ float rs[32];

    const int rt = blockIdx.x, b = blockIdx.y, n = blockIdx.z;
    const int s0 = rt * 32;
    const int tid = threadIdx.x, w = tid >> 5, lane = tid & 31;
    const size_t rowbase = (size_t)b * 1024;
    const int colbase = n * 64;

    // load Q tile (32 x 64) hi/lo
    {
        int row = tid >> 3, c8 = tid & 7;
        uint32_t so = (row * 72 + c8 * 8) * 2;
        size_t go = (rowbase + s0 + row) * 1024 + colbase + c8 * 8;
        *(uint4*)(sm + A_QH + so) = *(const uint4*)(LHI + go);
        *(uint4*)(sm + A_QL + so) = *(const uint4*)(LLO + go);
    }

    const float scale = 0.125f;
    // ---- QK^T: key tiles of 128; warp w handles keys [w*16, w*16+16) ----
    #pragma unroll 1
    for (int kt = 0; kt < 8; kt++) {
        __syncthreads();
        #pragma unroll
        for (int it = 0; it < 4; it++) {
            int row = (tid >> 3) + it * 32;
            int c8 = tid & 7;
            uint32_t so = (row * 72 + c8 * 8) * 2;
            size_t go = (rowbase + kt * 128 + row) * 1024 + colbase + c8 * 8;
            *(uint4*)(sm + A_KH + so) = *(const uint4*)(LHI + go);
            *(uint4*)(sm + A_KL + so) = *(const uint4*)(LLO + go);
        }
        __syncthreads();

        float sqk[2][2][4] = {};
        #pragma unroll
        for (int ks = 0; ks < 4; ks++) {
            unsigned qh[2][4], ql[2][4], kh[4], kl[4];
            uint32_t qb = sb + (((lane & 15)) * 72 + ks * 16 + (lane >> 4) * 8) * 2;
            ldsm4(qh[0], qb + A_QH);          ldsm4(ql[0], qb + A_QL);
            ldsm4(qh[1], qb + A_QH + 2304);   ldsm4(ql[1], qb + A_QL + 2304);
            uint32_t kb = sb + ((w * 16 + (lane & 15)) * 72 + ks * 16 + (lane >> 4) * 8) * 2;
            ldsm4(kh, kb + A_KH);             ldsm4(kl, kb + A_KL);
            #pragma unroll
            for (int mi = 0; mi < 2; mi++) {
                mma_bf16(sqk[mi][0], qh[mi][0],qh[mi][1],qh[mi][2],qh[mi][3], kh[0], kh[2]);
                mma_bf16(sqk[mi][1], qh[mi][0],qh[mi][1],qh[mi][2],qh[mi][3], kh[1], kh[3]);
                mma_bf16(sqk[mi][0], qh[mi][0],qh[mi][1],qh[mi][2],qh[mi][3], kl[0], kl[2]);
                mma_bf16(sqk[mi][1], qh[mi][0],qh[mi][1],qh[mi][2],qh[mi][3], kl[1], kl[3]);
                mma_bf16(sqk[mi][0], ql[mi][0],ql[mi][1],ql[mi][2],ql[mi][3], kh[0], kh[2]);
                mma_bf16(sqk[mi][1], ql[mi][0],ql[mi][1],ql[mi][2],ql[mi][3], kh[1], kh[3]);
            }
        }
        #pragma unroll
        for (int mi = 0; mi < 2; mi++) {
            int sr = mi * 16 + (lane >> 2);
            #pragma unroll
            for (int nj = 0; nj < 2; nj++) {
                int cc = kt * 128 + w * 16 + nj * 8 + 2 * (lane & 3);
                float2 v0 = make_float2(sqk[mi][nj][0] * scale, sqk[mi][nj][1] * scale);
                float2 v1 = make_float2(sqk[mi][nj][2] * scale, sqk[mi][nj][3] * scale);
                *(float2*)&scores[sr * 1028 + cc] = v0;
                *(float2*)&scores[(sr + 8) * 1028 + cc] = v1;
            }
        }
    }
    __syncthreads();

    // ---- softmax (fp32 exact): row = tid/8, 8 threads scan 128 each ----
    {
        const int row = tid >> 3, c = tid & 7;
        float* srow = scores + row * 1028 + c * 128;
        float m = -1e30f;
        #pragma unroll 8
        for (int i = 0; i < 128; i++) m = fmaxf(m, srow[i]);
        m = fmaxf(m, __shfl_xor_sync(0xffffffffu, m, 1));
        m = fmaxf(m, __shfl_xor_sync(0xffffffffu, m, 2));
        m = fmaxf(m, __shfl_xor_sync(0xffffffffu, m, 4));
        float sum = 0.f;
        #pragma unroll 8
        for (int i = 0; i < 128; i++) {
            float e = __expf(srow[i] - m);
            srow[i] = e;
            sum += e;
        }
        sum += __shfl_xor_sync(0xffffffffu, sum, 1);
        sum += __shfl_xor_sync(0xffffffffu, sum, 2);
        sum += __shfl_xor_sync(0xffffffffu, sum, 4);
        if (c == 0) rs[row] = 1.0f / sum;
    }
    __syncthreads();

    // ---- write normalized attention ----
    {
        float* ap = out_attn + ((size_t)(n * BB + b)) * SS * SS + (size_t)s0 * SS;
        #pragma unroll
        for (int it = 0; it < 32; it++) {
            int idx = tid + it * 256;
            int r = idx >> 8;
            int c4 = (idx & 255) << 2;
            float4 v = *(const float4*)&scores[r * 1028 + c4];
            float iv = rs[r];
            v.x *= iv; v.y *= iv; v.z *= iv; v.w *= iv;
            *(float4*)&ap[(size_t)r * SS + c4] = v;
        }
    }

    // ---- P @ V: warp grid 2m x 4n (warp = 16q x 16h), accumulate over jt ----
    const int wm = w >> 2, wn = w & 3;
    float pacc[2][4] = {};
    #pragma unroll 1
    for (int jt = 0; jt < 8; jt++) {
        __syncthreads();
        // V tile (reuse K region)
        #pragma unroll
        for (int it = 0; it < 4; it++) {
            int row = (tid >> 3) + it * 32;
            int c8 = tid & 7;
            uint32_t so = (row * 72 + c8 * 8) * 2;
            size_t go = (rowbase + jt * 128 + row) * 1024 + colbase + c8 * 8;
            *(uint4*)(sm + A_KH + so) = *(const uint4*)(LHI + go);
            *(uint4*)(sm + A_KL + so) = *(const uint4*)(LLO + go);
        }
        // P tile -> bf16 hi/lo
        #pragma unroll
        for (int it = 0; it < 16; it++) {
            int idx = tid + it * 256;
            int r = idx >> 7, c = idx & 127;
            float v = scores[r * 1028 + jt * 128 + c];
            __nv_bfloat16 h = __float2bfloat16(v);
            *(__nv_bfloat16*)(sm + A_PH + (r * 136 + c) * 2) = h;
            *(__nv_bfloat16*)(sm + A_PL + (r * 136 + c) * 2) =
                __float2bfloat16(v - __bfloat162float(h));
        }
        __syncthreads();

        #pragma unroll
        for (int ks = 0; ks < 8; ks++) {
            unsigned ph4[4], pl4[4], vh[4], vl[4];
            uint32_t pb = sb + ((wm * 16 + (lane & 15)) * 136 + ks * 16 + (lane >> 4) * 8) * 2;
            ldsm4(ph4, pb + A_PH);
            ldsm4(pl4, pb + A_PL);
            uint32_t vb = sb + ((ks * 16 + (lane & 15)) * 72 + wn * 16 + (lane >> 4) * 8) * 2;
            ldsm4t(vh, vb + A_KH);
            ldsm4t(vl, vb + A_KL);
            // trans B pairing: group0 {r0,r1}, group1 {r2,r3}
            mma_bf16(pacc[0], ph4[0],ph4[1],ph4[2],ph4[3], vh[0], vh[1]);
            mma_bf16(pacc[1], ph4[0],ph4[1],ph4[2],ph4[3], vh[2], vh[3]);
            mma_bf16(pacc[0], ph4[0],ph4[1],ph4[2],ph4[3], vl[0], vl[1]);
            mma_bf16(pacc[1], ph4[0],ph4[1],ph4[2],ph4[3], vl[2], vl[3]);
            mma_bf16(pacc[0], pl4[0],pl4[1],pl4[2],pl4[3], vh[0], vh[1]);
            mma_bf16(pacc[1], pl4[0],pl4[1],pl4[2],pl4[3], vh[2], vh[3]);
        }
    }

    // ---- epilogue: scale by 1/rowsum, write outh bf16 hi/lo ----
    {
        int qloc = wm * 16 + (lane >> 2);
        float iv0 = rs[qloc], iv1 = rs[qloc + 8];
        #pragma unroll
        for (int nj = 0; nj < 2; nj++) {
            int cc = colbase + wn * 16 + nj * 8 + 2 * (lane & 3);
            size_t go = (rowbase + s0 + qloc) * 1024 + cc;
            float v0 = pacc[nj][0] * iv0, v1 = pacc[nj][1] * iv0;
            float v2 = pacc[nj][2] * iv1, v3 = pacc[nj][3] * iv1;
            __nv_bfloat16 h0 = __float2bfloat16(v0), h1 = __float2bfloat16(v1);
            __nv_bfloat16 h2 = __float2bfloat16(v2), h3 = __float2bfloat16(v3);
            *(__nv_bfloat162*)(OHI + go) = __nv_bfloat162(h0, h1);
            *(__nv_bfloat162*)(OLO + go) = __nv_bfloat162(
                __float2bfloat16(v0 - __bfloat162float(h0)),
                __float2bfloat16(v1 - __bfloat162float(h1)));
            *(__nv_bfloat162*)(OHI + go + 8 * 1024) = __nv_bfloat162(h2, h3);
            *(__nv_bfloat162*)(OLO + go + 8 * 1024) = __nv_bfloat162(
                __float2bfloat16(v2 - __bfloat162float(h2)),
                __float2bfloat16(v3 - __bfloat162float(h3)));
        }
    }
}

// ---------------------------------------------------------------------------
// Layernorm per row of 1024
// ---------------------------------------------------------------------------
__global__ __launch_bounds__(256) void ln_kernel(float* __restrict__ y,
                                                 const float* __restrict__ g,
                                                 const float* __restrict__ bfn) {
    const int r = blockIdx.x;
    const int tid = threadIdx.x;
    const int lane = tid & 31, wid = tid >> 5;
    __shared__ float red1[8];
    __shared__ float red2[8];
    __shared__ float sh_mu, sh_rstd;

    float4 v = *(const float4*)&g_ypre[r * 1024 + tid * 4];
    float s = v.x + v.y + v.z + v.w;
    #pragma unroll
    for (int o = 16; o > 0; o >>= 1) s += __shfl_xor_sync(0xffffffffu, s, o);
    if (lane == 0) red1[wid] = s;
    __syncthreads();
    if (tid == 0) {
        float t = 0.f;
        #pragma unroll
        for (int i = 0; i < 8; i++) t += red1[i];
        sh_mu = t * (1.0f / 1024.0f);
    }
    __syncthreads();
    float mu = sh_mu;
    float dx = v.x - mu, dy = v.y - mu, dz = v.z - mu, dw = v.w - mu;
    float sq = dx * dx + dy * dy + dz * dz + dw * dw;
    #pragma unroll
    for (int o = 16; o > 0; o >>= 1) sq += __shfl_xor_sync(0xffffffffu, sq, o);
    if (lane == 0) red2[wid] = sq;
    __syncthreads();
    if (tid == 0) {
        float t = 0.f;
        #pragma unroll
        for (int i = 0; i < 8; i++) t += red2[i];
        sh_rstd = rsqrtf(t * (1.0f / 1024.0f) + 1e-5f);
    }
    __syncthreads();
    float rstd = sh_rstd;
    float4 gv = *(const float4*)&g[tid * 4];
    float4 bv = *(const float4*)&bfn[tid * 4];
    float4 o;
    o.x = dx * rstd * gv.x + bv.x;
    o.y = dy * rstd * gv.y + bv.y;
    o.z = dz * rstd * gv.z + bv.z;
    o.w = dw * rstd * gv.w + bv.w;
    *(float4*)&y[r * 1024 + tid * 4] = o;
}

// ---------------------------------------------------------------------------
extern "C" void kernel_launch(void* const* d_in, const int* in_sizes, int n_in,
                              void* d_out, int out_size) {
    const float* x   = (const float*)d_in[0];
    const float* w   = (const float*)d_in[1];
    const float* lw  = (const float*)d_in[2];
    const float* lb  = (const float*)d_in[3];
    const float* lng = (const float*)d_in[4];
    const float* lnb = (const float*)d_in[5];
    float* out = (float*)d_out;

    __nv_bfloat16 *xhi, *xlo, *wthi, *wtlo, *lwhi, *lwlo, *lhi, *llo, *ohhi, *ohlo;
    float *ypre;
    cudaGetSymbolAddress((void**)&xhi, g_xhi);   cudaGetSymbolAddress((void**)&xlo, g_xlo);
    cudaGetSymbolAddress((void**)&wthi, g_wThi); cudaGetSymbolAddress((void**)&wtlo, g_wTlo);
    cudaGetSymbolAddress((void**)&lwhi, g_lwhi); cudaGetSymbolAddress((void**)&lwlo, g_lwlo);
    cudaGetSymbolAddress((void**)&lhi, g_lhi);   cudaGetSymbolAddress((void**)&llo, g_llo);
    cudaGetSymbolAddress((void**)&ohhi, g_ohhi); cudaGetSymbolAddress((void**)&ohlo, g_ohlo);
    cudaGetSymbolAddress((void**)&ypre, g_ypre);

    cudaFuncSetAttribute(gemm_mma<0>, cudaFuncAttributeMaxDynamicSharedMemorySize, GSMEM);
    cudaFuncSetAttribute(gemm_mma<1>, cudaFuncAttributeMaxDynamicSharedMemorySize, GSMEM);
    cudaFuncSetAttribute(attn_kernel, cudaFuncAttributeMaxDynamicSharedMemorySize, ASMEM);

    // input splits
    split4_kernel<<<8192, 256>>>(x, xhi, xlo, MROWS * DD / 4);
    convw_kernel<<<4096, 256>>>(w);
    split4_kernel<<<1024, 256>>>(lw, lwhi, lwlo, DD * DD / 4);

    // head projection -> logits (bf16 hi/lo, concat layout)
    gemm_mma<0><<<dim3(64, 8), 256, GSMEM>>>(xhi, xlo, wthi, wtlo,
                                             lhi, llo, nullptr, nullptr, nullptr);
    // fused attention: writes attn matrix + outh (bf16 hi/lo)
    attn_kernel<<<dim3(32, 8, 16), 256, ASMEM>>>(lhi, llo, out + Y_SIZE, ohhi, ohlo);
    // output projection + residual + bias
    gemm_mma<1><<<dim3(64, 8), 256, GSMEM>>>(ohhi, ohlo, lwhi, lwlo,
                                             nullptr, nullptr, ypre, x, lb);
    // layernorm
    ln_kernel<<<MROWS, 256>>>(out, lng, lnb);
}

// round 7
// speedup vs baseline: 2.6942x; 1.4145x over previous
#include <cuda_runtime.h>
#include <cuda_bf16.h>
#include <cstdint>
#include <math.h>

#define BB 8
#define SS 1024
#define DD 1024
#define NH 16
#define HH 64
#define MROWS (BB*SS)            // 8192
#define Y_SIZE (BB*SS*DD)        // 8388608

// ---------------------------------------------------------------------------
// Scratch (device globals; no allocations allowed)
// ---------------------------------------------------------------------------
__device__ float g_ypre[MROWS*DD];                         // pre-layernorm y
__device__ __nv_bfloat16 g_xhi[MROWS*DD], g_xlo[MROWS*DD]; // x split
__device__ __nv_bfloat16 g_wThi[DD*DD], g_wTlo[DD*DD];     // proj B: [c=n*64+h][d]
__device__ __nv_bfloat16 g_lwhi[DD*DD], g_lwlo[DD*DD];     // outproj B: [d][k]
__device__ __nv_bfloat16 g_lhi[MROWS*DD], g_llo[MROWS*DD]; // logits split [r][n*64+h]
__device__ __nv_bfloat16 g_ohhi[MROWS*DD], g_ohlo[MROWS*DD]; // attn heads out split

// ---------------------------------------------------------------------------
// mma.sync / ldmatrix / cp.async helpers (base ISA)
// ---------------------------------------------------------------------------
__device__ __forceinline__ uint32_t smem_u32(const void* p) {
    uint32_t a;
    asm("{ .reg .u64 t; cvta.to.shared.u64 t, %1; cvt.u32.u64 %0, t; }" : "=r"(a) : "l"(p));
    return a;
}

__device__ __forceinline__ void mma_bf16(float c[4],
                                         unsigned a0, unsigned a1, unsigned a2, unsigned a3,
                                         unsigned b0, unsigned b1) {
    asm volatile("mma.sync.aligned.m16n8k16.row.col.f32.bf16.bf16.f32 "
        "{%0,%1,%2,%3}, {%4,%5,%6,%7}, {%8,%9}, {%0,%1,%2,%3};"
        : "+f"(c[0]), "+f"(c[1]), "+f"(c[2]), "+f"(c[3])
        : "r"(a0), "r"(a1), "r"(a2), "r"(a3), "r"(b0), "r"(b1));
}

__device__ __forceinline__ void ldsm4(unsigned r[4], uint32_t addr) {
    asm volatile("ldmatrix.sync.aligned.m8n8.x4.shared.b16 {%0,%1,%2,%3}, [%4];"
        : "=r"(r[0]), "=r"(r[1]), "=r"(r[2]), "=r"(r[3]) : "r"(addr));
}
__device__ __forceinline__ void ldsm4t(unsigned r[4], uint32_t addr) {
    asm volatile("ldmatrix.sync.aligned.m8n8.x4.trans.shared.b16 {%0,%1,%2,%3}, [%4];"
        : "=r"(r[0]), "=r"(r[1]), "=r"(r[2]), "=r"(r[3]) : "r"(addr));
}

__device__ __forceinline__ void cp16(uint32_t dst, const void* src) {
    asm volatile("cp.async.cg.shared.global [%0], [%1], 16;" :: "r"(dst), "l"(src));
}
#define CP_COMMIT() asm volatile("cp.async.commit_group;" ::: "memory")
#define CP_WAIT1()  asm volatile("cp.async.wait_group 1;" ::: "memory")
#define CP_WAIT0()  asm volatile("cp.async.wait_group 0;" ::: "memory")

// hi/lo split of float pair -> two packed bf16x2 regs
__device__ __forceinline__ void split2(float x, float y, unsigned& h, unsigned& l) {
    __nv_bfloat16 hx = __float2bfloat16(x), hy = __float2bfloat16(y);
    __nv_bfloat162 hp(hx, hy);
    __nv_bfloat162 lp(__float2bfloat16(x - __bfloat162float(hx)),
                      __float2bfloat16(y - __bfloat162float(hy)));
    h = *(unsigned*)&hp;
    l = *(unsigned*)&lp;
}

// ---------------------------------------------------------------------------
// Converters: fp32 -> bf16 hi/lo split
// ---------------------------------------------------------------------------
__global__ __launch_bounds__(256) void split4_kernel(const float* __restrict__ s,
                                                     __nv_bfloat16* __restrict__ hi,
                                                     __nv_bfloat16* __restrict__ lo, int n4) {
    int i = blockIdx.x * 256 + threadIdx.x;
    if (i >= n4) return;
    float4 v = ((const float4*)s)[i];
    unsigned h0, l0, h1, l1;
    split2(v.x, v.y, h0, l0);
    split2(v.z, v.w, h1, l1);
    ((unsigned*)hi)[i*2]   = h0;
    ((unsigned*)hi)[i*2+1] = h1;
    ((unsigned*)lo)[i*2]   = l0;
    ((unsigned*)lo)[i*2+1] = l1;
}

// w [NH][DD][HH] -> wT[c=n*64+h][d], split hi/lo
__global__ __launch_bounds__(256) void convw_kernel(const float* __restrict__ w) {
    int o = blockIdx.x * 256 + threadIdx.x;
    int c = o >> 10, d = o & 1023;
    int n = c >> 6, h = c & 63;
    float v = __ldg(&w[(n * 1024 + d) * 64 + h]);
    __nv_bfloat16 hv = __float2bfloat16(v);
    g_wThi[o] = hv;
    g_wTlo[o] = __float2bfloat16(v - __bfloat162float(hv));
}

// ---------------------------------------------------------------------------
// Dense GEMM via mma.sync, cp.async double-buffered.
// C[8192,1024] = A @ B^T  (bf16 hi/lo 3-pass). Block 128x128, K chunk 64.
// 8 warps (2m x 4n), warp tile 64x32. Smem row stride 72 bf16.
// EPI 0: C as bf16 hi/lo. EPI 1: fp32 C = acc + RX + BIAS.
// ---------------------------------------------------------------------------
#define GP_AH 0
#define GP_AL 18432
#define GP_BH 36864
#define GP_BL 55296
#define GBUF  73728
#define GSMEM (2*GBUF)    // 147456

template<int EPI>
__global__ __launch_bounds__(256) void gemm_mma(
    const __nv_bfloat16* __restrict__ Ah, const __nv_bfloat16* __restrict__ Al,
    const __nv_bfloat16* __restrict__ Bh, const __nv_bfloat16* __restrict__ Bl,
    __nv_bfloat16* __restrict__ Chi, __nv_bfloat16* __restrict__ Clo,
    float* __restrict__ Cf, const float* __restrict__ RX, const float* __restrict__ BIAS)
{
    extern __shared__ char sm[];
    const uint32_t sb = smem_u32(sm);
    const int tid = threadIdx.x, w = tid >> 5, lane = tid & 31;
    const int wm = w >> 2, wn = w & 3;
    const int r0 = blockIdx.x * 128, c0 = blockIdx.y * 128;
    const int lrow = tid >> 3, lc8 = tid & 7;

    float acc[4][4][4] = {};

    // prefetch chunk 0
    auto load_chunk = [&](int buf, int k0) {
        const uint32_t bb = sb + buf * GBUF;
        #pragma unroll
        for (int it = 0; it < 4; it++) {
            int rr = lrow + it * 32;
            size_t goA = (size_t)(r0 + rr) * 1024 + k0 + lc8 * 8;
            size_t goB = (size_t)(c0 + rr) * 1024 + k0 + lc8 * 8;
            uint32_t so = (rr * 72 + lc8 * 8) * 2;
            cp16(bb + GP_AH + so, Ah + goA);
            cp16(bb + GP_AL + so, Al + goA);
            cp16(bb + GP_BH + so, Bh + goB);
            cp16(bb + GP_BL + so, Bl + goB);
        }
    };

    load_chunk(0, 0);
    CP_COMMIT();

    #pragma unroll 1
    for (int ch = 0; ch < 16; ch++) {
        if (ch < 15) {
            load_chunk((ch + 1) & 1, (ch + 1) * 64);
            CP_COMMIT();
            CP_WAIT1();
        } else {
            CP_WAIT0();
        }
        __syncthreads();
        const uint32_t bb = sb + (ch & 1) * GBUF;
        #pragma unroll
        for (int ks = 0; ks < 4; ks++) {
            unsigned ah[4][4], al[4][4], bh[2][4], bl[2][4];
            uint32_t abase = bb + ((wm * 64 + (lane & 15)) * 72 + ks * 16 + (lane >> 4) * 8) * 2;
            #pragma unroll
            for (int mi = 0; mi < 4; mi++) {
                ldsm4(ah[mi], abase + GP_AH + mi * 2304);
                ldsm4(al[mi], abase + GP_AL + mi * 2304);
            }
            uint32_t bbase = bb + ((wn * 32 + (lane & 15)) * 72 + ks * 16 + (lane >> 4) * 8) * 2;
            #pragma unroll
            for (int ni = 0; ni < 2; ni++) {
                ldsm4(bh[ni], bbase + GP_BH + ni * 2304);
                ldsm4(bl[ni], bbase + GP_BL + ni * 2304);
            }
            #pragma unroll
            for (int mi = 0; mi < 4; mi++)
                #pragma unroll
                for (int ni = 0; ni < 2; ni++) {
                    mma_bf16(acc[mi][2*ni],   ah[mi][0],ah[mi][1],ah[mi][2],ah[mi][3], bh[ni][0], bh[ni][2]);
                    mma_bf16(acc[mi][2*ni+1], ah[mi][0],ah[mi][1],ah[mi][2],ah[mi][3], bh[ni][1], bh[ni][3]);
                    mma_bf16(acc[mi][2*ni],   ah[mi][0],ah[mi][1],ah[mi][2],ah[mi][3], bl[ni][0], bl[ni][2]);
                    mma_bf16(acc[mi][2*ni+1], ah[mi][0],ah[mi][1],ah[mi][2],ah[mi][3], bl[ni][1], bl[ni][3]);
                    mma_bf16(acc[mi][2*ni],   al[mi][0],al[mi][1],al[mi][2],al[mi][3], bh[ni][0], bh[ni][2]);
                    mma_bf16(acc[mi][2*ni+1], al[mi][0],al[mi][1],al[mi][2],al[mi][3], bh[ni][1], bh[ni][3]);
                }
        }
        __syncthreads();
    }

    // epilogue
    #pragma unroll
    for (int mi = 0; mi < 4; mi++) {
        int rr = r0 + wm * 64 + mi * 16 + (lane >> 2);
        #pragma unroll
        for (int nj = 0; nj < 4; nj++) {
            int cc = c0 + wn * 32 + nj * 8 + 2 * (lane & 3);
            if (EPI == 0) {
                #pragma unroll
                for (int half = 0; half < 2; half++) {
                    unsigned h, l;
                    split2(acc[mi][nj][half*2], acc[mi][nj][half*2+1], h, l);
                    size_t go = (size_t)(rr + half*8) * 1024 + cc;
                    *(unsigned*)(Chi + go) = h;
                    *(unsigned*)(Clo + go) = l;
                }
            } else {
                #pragma unroll
                for (int half = 0; half < 2; half++) {
                    size_t go = (size_t)(rr + half*8) * 1024 + cc;
                    float2 xv = *(const float2*)(RX + go);
                    float2 bv = *(const float2*)(BIAS + cc);
                    float2 o;
                    o.x = acc[mi][nj][half*2]   + xv.x + bv.x;
                    o.y = acc[mi][nj][half*2+1] + xv.y + bv.y;
                    *(float2*)(Cf + go) = o;
                }
            }
        }
    }
}

// ---------------------------------------------------------------------------
// Fused attention per (n, b, 32-row tile), tensorized + cp.async dbuf.
// scores stride = 1032 floats (==8 mod 32 banks: conflict-free epilogue,
// stride-8 conflict-free softmax scan, and conflict-free fp32 P-frag reads).
// PV reads P as fp32 from scores and hi/lo-splits in registers (no smem
// conversion phase).
// ---------------------------------------------------------------------------
#define SCSTR 1032
#define A_SC  0                         // 32*1032*4 = 132096
#define A_QH  132096                    // 32*72*2 = 4608
#define A_QL  136704
#define A_KB  141312                    // 2 bufs x (KH 18432 + KL 18432)
#define A_KBUF 36864
#define ASMEM (A_KB + 2*A_KBUF)         // 215040

__global__ __launch_bounds__(256) void attn_kernel(
    const __nv_bfloat16* __restrict__ LHI, const __nv_bfloat16* __restrict__ LLO,
    float* __restrict__ out_attn,
    __nv_bfloat16* __restrict__ OHI, __nv_bfloat16* __restrict__ OLO)
{
    extern __shared__ char sm[];
    const uint32_t sb = smem_u32(sm);
    float* scores = (float*)sm;
    __shared__ float rs[32];

    const int rt = blockIdx.x, b = blockIdx.y, n = blockIdx.z;
    const int s0 = rt * 32;
    const int tid = threadIdx.x, w = tid >> 5, lane = tid & 31;
    const size_t rowbase = (size_t)b * 1024;
    const int colbase = n * 64;
    const int lrow = tid >> 3, lc8 = tid & 7;

    auto load_kv = [&](int buf, int tile) {
        const uint32_t bh = sb + A_KB + buf * A_KBUF;
        #pragma unroll
        for (int it = 0; it < 4; it++) {
            int row = lrow + it * 32;
            size_t go = (rowbase + tile * 128 + row) * 1024 + colbase + lc8 * 8;
            uint32_t so = (row * 72 + lc8 * 8) * 2;
            cp16(bh + so,         LHI + go);
            cp16(bh + 18432 + so, LLO + go);
        }
    };

    // load Q tile (32 x 64) hi/lo (direct) + prefetch K tile 0
    load_kv(0, 0);
    CP_COMMIT();
    {
        int row = tid >> 3, c8 = tid & 7;
        uint32_t so = (row * 72 + c8 * 8) * 2;
        size_t go = (rowbase + s0 + row) * 1024 + colbase + c8 * 8;
        *(uint4*)(sm + A_QH + so) = *(const uint4*)(LHI + go);
        *(uint4*)(sm + A_QL + so) = *(const uint4*)(LLO + go);
    }

    const float scale = 0.125f;
    // ---- QK^T: 8 key tiles of 128, double-buffered ----
    #pragma unroll 1
    for (int kt = 0; kt < 8; kt++) {
        if (kt < 7) {
            load_kv((kt + 1) & 1, kt + 1);
            CP_COMMIT();
            CP_WAIT1();
        } else {
            CP_WAIT0();
        }
        __syncthreads();
        const uint32_t kbase = sb + A_KB + (kt & 1) * A_KBUF;

        float sqk[2][2][4] = {};
        #pragma unroll
        for (int ks = 0; ks < 4; ks++) {
            unsigned qh[2][4], ql[2][4], kh[4], kl[4];
            uint32_t qb = sb + (((lane & 15)) * 72 + ks * 16 + (lane >> 4) * 8) * 2;
            ldsm4(qh[0], qb + A_QH);          ldsm4(ql[0], qb + A_QL);
            ldsm4(qh[1], qb + A_QH + 2304);   ldsm4(ql[1], qb + A_QL + 2304);
            uint32_t kb = kbase + ((w * 16 + (lane & 15)) * 72 + ks * 16 + (lane >> 4) * 8) * 2;
            ldsm4(kh, kb);                    ldsm4(kl, kb + 18432);
            #pragma unroll
            for (int mi = 0; mi < 2; mi++) {
                mma_bf16(sqk[mi][0], qh[mi][0],qh[mi][1],qh[mi][2],qh[mi][3], kh[0], kh[2]);
                mma_bf16(sqk[mi][1], qh[mi][0],qh[mi][1],qh[mi][2],qh[mi][3], kh[1], kh[3]);
                mma_bf16(sqk[mi][0], qh[mi][0],qh[mi][1],qh[mi][2],qh[mi][3], kl[0], kl[2]);
                mma_bf16(sqk[mi][1], qh[mi][0],qh[mi][1],qh[mi][2],qh[mi][3], kl[1], kl[3]);
                mma_bf16(sqk[mi][0], ql[mi][0],ql[mi][1],ql[mi][2],ql[mi][3], kh[0], kh[2]);
                mma_bf16(sqk[mi][1], ql[mi][0],ql[mi][1],ql[mi][2],ql[mi][3], kh[1], kh[3]);
            }
        }
        #pragma unroll
        for (int mi = 0; mi < 2; mi++) {
            int sr = mi * 16 + (lane >> 2);
            #pragma unroll
            for (int nj = 0; nj < 2; nj++) {
                int cc = kt * 128 + w * 16 + nj * 8 + 2 * (lane & 3);
                *(float2*)&scores[sr * SCSTR + cc] =
                    make_float2(sqk[mi][nj][0] * scale, sqk[mi][nj][1] * scale);
                *(float2*)&scores[(sr + 8) * SCSTR + cc] =
                    make_float2(sqk[mi][nj][2] * scale, sqk[mi][nj][3] * scale);
            }
        }
        __syncthreads();
    }

    // ---- softmax (fp32 exact): row = tid/8, stride-8 conflict-free scan ----
    {
        const int row = tid >> 3, c = tid & 7;
        float* srow = scores + row * SCSTR;
        float m = -1e30f;
        #pragma unroll 8
        for (int i = 0; i < 128; i++) m = fmaxf(m, srow[c + 8 * i]);
        m = fmaxf(m, __shfl_xor_sync(0xffffffffu, m, 1));
        m = fmaxf(m, __shfl_xor_sync(0xffffffffu, m, 2));
        m = fmaxf(m, __shfl_xor_sync(0xffffffffu, m, 4));
        float sum = 0.f;
        #pragma unroll 8
        for (int i = 0; i < 128; i++) {
            float e = __expf(srow[c + 8 * i] - m);
            srow[c + 8 * i] = e;
            sum += e;
        }
        sum += __shfl_xor_sync(0xffffffffu, sum, 1);
        sum += __shfl_xor_sync(0xffffffffu, sum, 2);
        sum += __shfl_xor_sync(0xffffffffu, sum, 4);
        if (c == 0) rs[row] = 1.0f / sum;
    }
    __syncthreads();

    // prefetch V tile 0 (overlaps the attn gmem write below)
    load_kv(0, 0);
    CP_COMMIT();

    // ---- write normalized attention ----
    {
        float* ap = out_attn + ((size_t)(n * BB + b)) * SS * SS + (size_t)s0 * SS;
        #pragma unroll
        for (int it = 0; it < 32; it++) {
            int idx = tid + it * 256;
            int r = idx >> 8;
            int c4 = (idx & 255) << 2;
            float4 v = *(const float4*)&scores[r * SCSTR + c4];
            float iv = rs[r];
            v.x *= iv; v.y *= iv; v.z *= iv; v.w *= iv;
            *(float4*)&ap[(size_t)r * SS + c4] = v;
        }
    }

    // ---- P @ V: warps 2m x 4n (16q x 16h each); P frags read fp32 from
    //      scores + register hi/lo split; V double-buffered ----
    const int wm = w >> 2, wn = w & 3;
    float pacc[2][4] = {};
    const int qr = wm * 16 + (lane >> 2);
    const int kcl = (lane & 3) * 2;
    #pragma unroll 1
    for (int jt = 0; jt < 8; jt++) {
        if (jt < 7) {
            load_kv((jt + 1) & 1, jt + 1);
            CP_COMMIT();
            CP_WAIT1();
        } else {
            CP_WAIT0();
        }
        __syncthreads();
        const uint32_t vbase = sb + A_KB + (jt & 1) * A_KBUF;

        #pragma unroll
        for (int ks = 0; ks < 8; ks++) {
            const int kc = jt * 128 + ks * 16 + kcl;
            float2 p00 = *(const float2*)&scores[qr * SCSTR + kc];
            float2 p10 = *(const float2*)&scores[(qr + 8) * SCSTR + kc];
            float2 p01 = *(const float2*)&scores[qr * SCSTR + kc + 8];
            float2 p11 = *(const float2*)&scores[(qr + 8) * SCSTR + kc + 8];
            unsigned ph4[4], pl4[4];
            split2(p00.x, p00.y, ph4[0], pl4[0]);
            split2(p10.x, p10.y, ph4[1], pl4[1]);
            split2(p01.x, p01.y, ph4[2], pl4[2]);
            split2(p11.x, p11.y, ph4[3], pl4[3]);

            unsigned vh[4], vl[4];
            uint32_t vb = vbase + ((ks * 16 + (lane & 15)) * 72 + wn * 16 + (lane >> 4) * 8) * 2;
            ldsm4t(vh, vb);
            ldsm4t(vl, vb + 18432);

            mma_bf16(pacc[0], ph4[0],ph4[1],ph4[2],ph4[3], vh[0], vh[1]);
            mma_bf16(pacc[1], ph4[0],ph4[1],ph4[2],ph4[3], vh[2], vh[3]);
            mma_bf16(pacc[0], ph4[0],ph4[1],ph4[2],ph4[3], vl[0], vl[1]);
            mma_bf16(pacc[1], ph4[0],ph4[1],ph4[2],ph4[3], vl[2], vl[3]);
            mma_bf16(pacc[0], pl4[0],pl4[1],pl4[2],pl4[3], vh[0], vh[1]);
            mma_bf16(pacc[1], pl4[0],pl4[1],pl4[2],pl4[3], vh[2], vh[3]);
        }
        __syncthreads();
    }

    // ---- epilogue: scale by 1/rowsum, write outh bf16 hi/lo ----
    {
        float iv0 = rs[qr], iv1 = rs[qr + 8];
        #pragma unroll
        for (int nj = 0; nj < 2; nj++) {
            int cc = colbase + wn * 16 + nj * 8 + 2 * (lane & 3);
            size_t go = (rowbase + s0 + qr) * 1024 + cc;
            unsigned h0, l0, h1, l1;
            split2(pacc[nj][0] * iv0, pacc[nj][1] * iv0, h0, l0);
            split2(pacc[nj][2] * iv1, pacc[nj][3] * iv1, h1, l1);
            *(unsigned*)(OHI + go) = h0;
            *(unsigned*)(OLO + go) = l0;
            *(unsigned*)(OHI + go + 8 * 1024) = h1;
            *(unsigned*)(OLO + go + 8 * 1024) = l1;
        }
    }
}

// ---------------------------------------------------------------------------
// Layernorm per row of 1024
// ---------------------------------------------------------------------------
__global__ __launch_bounds__(256) void ln_kernel(float* __restrict__ y,
                                                 const float* __restrict__ g,
                                                 const float* __restrict__ bfn) {
    const int r = blockIdx.x;
    const int tid = threadIdx.x;
    const int lane = tid & 31, wid = tid >> 5;
    __shared__ float red1[8];
    __shared__ float red2[8];
    __shared__ float sh_mu, sh_rstd;

    float4 v = *(const float4*)&g_ypre[r * 1024 + tid * 4];
    float s = v.x + v.y + v.z + v.w;
    #pragma unroll
    for (int o = 16; o > 0; o >>= 1) s += __shfl_xor_sync(0xffffffffu, s, o);
    if (lane == 0) red1[wid] = s;
    __syncthreads();
    if (tid == 0) {
        float t = 0.f;
        #pragma unroll
        for (int i = 0; i < 8; i++) t += red1[i];
        sh_mu = t * (1.0f / 1024.0f);
    }
    __syncthreads();
    float mu = sh_mu;
    float dx = v.x - mu, dy = v.y - mu, dz = v.z - mu, dw = v.w - mu;
    float sq = dx * dx + dy * dy + dz * dz + dw * dw;
    #pragma unroll
    for (int o = 16; o > 0; o >>= 1) sq += __shfl_xor_sync(0xffffffffu, sq, o);
    if (lane == 0) red2[wid] = sq;
    __syncthreads();
    if (tid == 0) {
        float t = 0.f;
        #pragma unroll
        for (int i = 0; i < 8; i++) t += red2[i];
        sh_rstd = rsqrtf(t * (1.0f / 1024.0f) + 1e-5f);
    }
    __syncthreads();
    float rstd = sh_rstd;
    float4 gv = *(const float4*)&g[tid * 4];
    float4 bv = *(const float4*)&bfn[tid * 4];
    float4 o;
    o.x = dx * rstd * gv.x + bv.x;
    o.y = dy * rstd * gv.y + bv.y;
    o.z = dz * rstd * gv.z + bv.z;
    o.w = dw * rstd * gv.w + bv.w;
    *(float4*)&y[r * 1024 + tid * 4] = o;
}

// ---------------------------------------------------------------------------
extern "C" void kernel_launch(void* const* d_in, const int* in_sizes, int n_in,
                              void* d_out, int out_size) {
    const float* x   = (const float*)d_in[0];
    const float* w   = (const float*)d_in[1];
    const float* lw  = (const float*)d_in[2];
    const float* lb  = (const float*)d_in[3];
    const float* lng = (const float*)d_in[4];
    const float* lnb = (const float*)d_in[5];
    float* out = (float*)d_out;

    __nv_bfloat16 *xhi, *xlo, *wthi, *wtlo, *lwhi, *lwlo, *lhi, *llo, *ohhi, *ohlo;
    float *ypre;
    cudaGetSymbolAddress((void**)&xhi, g_xhi);   cudaGetSymbolAddress((void**)&xlo, g_xlo);
    cudaGetSymbolAddress((void**)&wthi, g_wThi); cudaGetSymbolAddress((void**)&wtlo, g_wTlo);
    cudaGetSymbolAddress((void**)&lwhi, g_lwhi); cudaGetSymbolAddress((void**)&lwlo, g_lwlo);
    cudaGetSymbolAddress((void**)&lhi, g_lhi);   cudaGetSymbolAddress((void**)&llo, g_llo);
    cudaGetSymbolAddress((void**)&ohhi, g_ohhi); cudaGetSymbolAddress((void**)&ohlo, g_ohlo);
    cudaGetSymbolAddress((void**)&ypre, g_ypre);

    cudaFuncSetAttribute(gemm_mma<0>, cudaFuncAttributeMaxDynamicSharedMemorySize, GSMEM);
    cudaFuncSetAttribute(gemm_mma<1>, cudaFuncAttributeMaxDynamicSharedMemorySize, GSMEM);
    cudaFuncSetAttribute(attn_kernel, cudaFuncAttributeMaxDynamicSharedMemorySize, ASMEM);

    // input splits
    split4_kernel<<<8192, 256>>>(x, xhi, xlo, MROWS * DD / 4);
    convw_kernel<<<4096, 256>>>(w);
    split4_kernel<<<1024, 256>>>(lw, lwhi, lwlo, DD * DD / 4);

    // head projection -> logits (bf16 hi/lo, concat layout)
    gemm_mma<0><<<dim3(64, 8), 256, GSMEM>>>(xhi, xlo, wthi, wtlo,
                                             lhi, llo, nullptr, nullptr, nullptr);
    // fused attention: writes attn matrix + outh (bf16 hi/lo)
    attn_kernel<<<dim3(32, 8, 16), 256, ASMEM>>>(lhi, llo, out + Y_SIZE, ohhi, ohlo);
    // output projection + residual + bias
    gemm_mma<1><<<dim3(64, 8), 256, GSMEM>>>(ohhi, ohlo, lwhi, lwlo,
                                             nullptr, nullptr, ypre, x, lb);
    // layernorm
    ln_kernel<<<MROWS, 256>>>(out, lng, lnb);
}